// round 13
// baseline (speedup 1.0000x reference)
#include <cuda_runtime.h>
#include <cstdint>

// IDWT (inverse Haar wavelet). Inputs LL,LH,HL,HH: [B=16,C=64,h=128,w=128] f32.
// Output: [B,C,256,256] f32. Closed-form 2x2 butterfly, s^2 = 0.5.
//
// R5 structure (float2 loads / float4 stores, all warp-contiguous, block=256)
// with DEFAULT write-back stores (plain assignment) instead of __stcs:
// tests whether L2's default writeback aggregation schedules the DRAM write
// stream better than evict-first marking. Loads keep the streaming hint
// (measured neutral, keeps reads from polluting L2 ahead of writebacks).

static constexpr int C2 = 64;                       // float2s per input row
static constexpr int NROWS = 16 * 64 * 128;         // B*C*h = 131072
static constexpr int NTHREADS_TOTAL = NROWS * C2;   // 8,388,608
static constexpr int BLOCK = 256;

__global__ __launch_bounds__(BLOCK) void idwt_haar_kernel(
    const float2* __restrict__ LL,
    const float2* __restrict__ LH,
    const float2* __restrict__ HL,
    const float2* __restrict__ HH,
    float4* __restrict__ out)
{
    int tid = blockIdx.x * BLOCK + threadIdx.x;   // grid covers domain exactly

    // input float2 index == tid  (row-major [NROWS, 64])
    float2 ll = __ldcs(&LL[tid]);
    float2 lh = __ldcs(&LH[tid]);
    float2 hl = __ldcs(&HL[tid]);
    float2 hh = __ldcs(&HH[tid]);

    int row = tid >> 6;        // bc*128 + i
    int c   = tid & 63;        // output float4 column index

    int bc = row >> 7;
    int i  = row & 127;

    // output [bc][256][256] f32 -> float4 row stride 64
    size_t obase = ((size_t)bc * 256 + 2 * i) * 64 + (size_t)c;

    float4 t, b;
    {
        float s0 = ll.x + hh.x, d0 = ll.x - hh.x;
        float s1 = lh.x + hl.x, d1 = lh.x - hl.x;
        t.x = 0.5f * (s0 - s1);
        t.y = 0.5f * (d0 + d1);
        b.x = 0.5f * (d0 - d1);
        b.y = 0.5f * (s0 + s1);
    }
    {
        float s0 = ll.y + hh.y, d0 = ll.y - hh.y;
        float s1 = lh.y + hl.y, d1 = lh.y - hl.y;
        t.z = 0.5f * (s0 - s1);
        t.w = 0.5f * (d0 + d1);
        b.z = 0.5f * (d0 - d1);
        b.w = 0.5f * (s0 + s1);
    }

    out[obase] = t;            // default .wb stores
    out[obase + 64] = b;
}

extern "C" void kernel_launch(void* const* d_in, const int* in_sizes, int n_in,
                              void* d_out, int out_size)
{
    const float2* LL = (const float2*)d_in[0];
    const float2* LH = (const float2*)d_in[1];
    const float2* HL = (const float2*)d_in[2];
    const float2* HH = (const float2*)d_in[3];

    float4* out = (float4*)d_out;

    int blocks = NTHREADS_TOTAL / BLOCK;  // 32768
    idwt_haar_kernel<<<blocks, BLOCK>>>(LL, LH, HL, HH, out);
}

// round 14
// speedup vs baseline: 1.0283x; 1.0283x over previous
#include <cuda_runtime.h>
#include <cstdint>

// IDWT (inverse Haar wavelet). Inputs LL,LH,HL,HH: [B=16,C=64,h=128,w=128] f32.
// Output: [B,C,256,256] f32. Closed-form 2x2 butterfly, s^2 = 0.5.
//
// FINAL KERNEL (R5 configuration — best measured of 13 rounds):
//   - one thread per output float4-column pair
//   - loads one float2 per band: each warp load instr covers 256B contiguous
//   - stores one float4 to row 2i and one to row 2i+1: each warp store instr
//     covers 512B contiguous; each CTA writes a contiguous 8KB output block
//   - __ldcs/__stcs streaming hints; block=256, grid=32768, 20 regs, occ ~83%
//
// Measured plateau: 73.7-75.3us kernel, 6.4-6.6 TB/s (81-83% of HBM spec) —
// the memory-controller read/write turnaround ceiling. Ruled out by direct
// measurement: wider per-thread work (reg->occ cliff), 128/512 blocks,
// persistent grid, .wt stores (-8%), .wb stores (neutral), warp-owns-row
// layout, TMA path (LTS cap is path-independent per B300 microarch data).

static constexpr int C2 = 64;                       // float2s per input row
static constexpr int NROWS = 16 * 64 * 128;         // B*C*h = 131072
static constexpr int NTHREADS_TOTAL = NROWS * C2;   // 8,388,608
static constexpr int BLOCK = 256;

__global__ __launch_bounds__(BLOCK) void idwt_haar_kernel(
    const float2* __restrict__ LL,
    const float2* __restrict__ LH,
    const float2* __restrict__ HL,
    const float2* __restrict__ HH,
    float4* __restrict__ out)
{
    int tid = blockIdx.x * BLOCK + threadIdx.x;   // grid covers domain exactly

    // input float2 index == tid  (row-major [NROWS, 64])
    float2 ll = __ldcs(&LL[tid]);
    float2 lh = __ldcs(&LH[tid]);
    float2 hl = __ldcs(&HL[tid]);
    float2 hh = __ldcs(&HH[tid]);

    int row = tid >> 6;        // bc*128 + i
    int c   = tid & 63;        // output float4 column index

    int bc = row >> 7;
    int i  = row & 127;

    // output [bc][256][256] f32 -> float4 row stride 64
    size_t obase = ((size_t)bc * 256 + 2 * i) * 64 + (size_t)c;

    float4 t, b;
    {
        float s0 = ll.x + hh.x, d0 = ll.x - hh.x;
        float s1 = lh.x + hl.x, d1 = lh.x - hl.x;
        t.x = 0.5f * (s0 - s1);
        t.y = 0.5f * (d0 + d1);
        b.x = 0.5f * (d0 - d1);
        b.y = 0.5f * (s0 + s1);
    }
    {
        float s0 = ll.y + hh.y, d0 = ll.y - hh.y;
        float s1 = lh.y + hl.y, d1 = lh.y - hl.y;
        t.z = 0.5f * (s0 - s1);
        t.w = 0.5f * (d0 + d1);
        b.z = 0.5f * (d0 - d1);
        b.w = 0.5f * (s0 + s1);
    }

    __stcs(&out[obase], t);
    __stcs(&out[obase + 64], b);
}

extern "C" void kernel_launch(void* const* d_in, const int* in_sizes, int n_in,
                              void* d_out, int out_size)
{
    const float2* LL = (const float2*)d_in[0];
    const float2* LH = (const float2*)d_in[1];
    const float2* HL = (const float2*)d_in[2];
    const float2* HH = (const float2*)d_in[3];

    float4* out = (float4*)d_out;

    int blocks = NTHREADS_TOTAL / BLOCK;  // 32768
    idwt_haar_kernel<<<blocks, BLOCK>>>(LL, LH, HL, HH, out);
}